// round 9
// baseline (speedup 1.0000x reference)
#include <cuda_runtime.h>
#include <cuda_fp16.h>
#include <cstdint>
#include <math.h>

#define BB   64
#define NN   4096
#define DD   64
#define HH   256
#define SS   1024
#define TOT  49152   // 3 * D * H
#define WPB  24576   // half2 words per batch (3*D*H/2)

// raw hypernet output (k1 -> k2)
__device__ float g_params[BB * (size_t)TOT];
// normalized fp16 weights, half2-packed along k, XOR-swizzled (k2 -> k3)
__device__ uint32_t g_wT[BB * (size_t)WPB];
// s pre-packed to half2 (k0 -> k1): [64][512] words, word kp = (k=2kp, 2kp+1)
__device__ uint32_t g_s16[BB * (SS / 2)];

// ======================= helpers =======================
__device__ __forceinline__ float tanha(float x) {
    float y;
    asm("tanh.approx.f32 %0, %1;" : "=f"(y) : "f"(x));
    return y;
}
__device__ __forceinline__ uint32_t pack2(float lo, float hi) {
    __half2 h = __floats2half2_rn(lo, hi);
    return *(uint32_t*)&h;
}
__device__ __forceinline__ uint32_t smem_u32(const void* p) {
    uint32_t a;
    asm("{ .reg .u64 t; cvta.to.shared.u64 t, %1; cvt.u32.u64 %0, t; }" : "=r"(a) : "l"(p));
    return a;
}
__device__ __forceinline__ void cpa16(uint32_t dst, const void* src) {
    asm volatile("cp.async.cg.shared.global [%0], [%1], 16;" :: "r"(dst), "l"(src));
}
#define CP_COMMIT() asm volatile("cp.async.commit_group;" ::: "memory")
#define CP_WAIT0()  asm volatile("cp.async.wait_group 0;" ::: "memory")
#define CP_WAIT2()  asm volatile("cp.async.wait_group 2;" ::: "memory")

// D += A * B  (m16n8k16, fp16 inputs, fp32 accum)
__device__ __forceinline__ void mma_f16(float* d, const uint32_t* a, uint32_t b0, uint32_t b1) {
    asm volatile("mma.sync.aligned.m16n8k16.row.col.f32.f16.f16.f32 "
                 "{%0,%1,%2,%3}, {%4,%5,%6,%7}, {%8,%9}, {%0,%1,%2,%3};"
                 : "+f"(d[0]), "+f"(d[1]), "+f"(d[2]), "+f"(d[3])
                 : "r"(a[0]), "r"(a[1]), "r"(a[2]), "r"(a[3]), "r"(b0), "r"(b1));
}

// ======================= kernel 0: pack s -> half2 =======================
__global__ __launch_bounds__(256) void k0_pack_s(const float* __restrict__ s) {
    const int tid = blockIdx.x * 256 + threadIdx.x;
    #pragma unroll
    for (int i = 0; i < 8; i++) {
        int idx = tid + i * 4096;          // 32768 words total
        float2 v = *(const float2*)(s + 2 * idx);
        g_s16[idx] = pack2(v.x, v.y);
    }
}

// ======================= kernel 1: hypernet GEMM, fp16 mma, 4-stage cp.async =======================
// A stage: [64][20] half2 words (only 16 used; stride 20 -> CF banks).
// B stage: [32][132] fp32 (stride 132 -> CF for paired-row half2 packing).
#define K1_AW   (64 * 20)                  // 1280 words/stage
#define K1_BW   (32 * 132)                 // 4224 words/stage
#define K1_STGW (K1_AW + K1_BW)            // 5504
#define K1_SMEM (4 * K1_STGW * 4)          // 88064 B

__global__ __launch_bounds__(256) void k1_mma(const float* __restrict__ W,
                                              const float* __restrict__ bias) {
    extern __shared__ uint32_t sk1[];
    uint32_t* A0 = sk1;                     // 4 * 1280 words
    float* B0 = (float*)(sk1 + 4 * K1_AW);  // 4 * 4224 floats
    const int n0  = blockIdx.x * 128;
    const int tid = threadIdx.x;
    const int w = tid >> 5, lane = tid & 31;
    const int r = lane >> 2, q = lane & 3;
    const int m0 = (w & 1) * 32, nw = (w >> 1) * 32;
    const uint32_t sbA = smem_u32(A0), sbB = smem_u32(B0);

    #define K1_LOAD(st, k0) do {                                                   \
        {                                                                          \
            int row = tid >> 2, cc = tid & 3;                                      \
            cpa16(sbA + (uint32_t)((st) * K1_AW + row * 20 + cc * 4) * 4,          \
                  g_s16 + row * (SS / 2) + (k0) / 2 + cc * 4);                     \
        }                                                                          \
        _Pragma("unroll")                                                          \
        for (int i = 0; i < 4; i++) {                                              \
            int c = tid + i * 256;                                                 \
            int row = c >> 5, cc = c & 31;                                         \
            cpa16(sbB + (uint32_t)((st) * K1_BW + row * 132 + cc * 4) * 4,         \
                  W + (size_t)((k0) + row) * TOT + n0 + cc * 4);                   \
        }                                                                          \
    } while (0)

    float acc[2][4][4];
    #pragma unroll
    for (int mf = 0; mf < 2; mf++)
        #pragma unroll
        for (int nf = 0; nf < 4; nf++)
            acc[mf][nf][0] = acc[mf][nf][1] = acc[mf][nf][2] = acc[mf][nf][3] = 0.f;

    K1_LOAD(0, 0);  CP_COMMIT();
    K1_LOAD(1, 32); CP_COMMIT();
    K1_LOAD(2, 64); CP_COMMIT();

    for (int ks = 0; ks < 32; ks++) {
        CP_WAIT2();
        __syncthreads();
        const int st = ks & 3;
        const uint32_t* A = A0 + st * K1_AW;
        const float* Bp = B0 + st * K1_BW;
        #pragma unroll
        for (int t = 0; t < 2; t++) {       // two k16 tiles per 32-k stage
            uint32_t a[2][4];
            #pragma unroll
            for (int mf = 0; mf < 2; mf++) {
                const int mr = m0 + mf * 16 + r;
                a[mf][0] = A[mr * 20 + t * 8 + q];
                a[mf][1] = A[(mr + 8) * 20 + t * 8 + q];
                a[mf][2] = A[mr * 20 + t * 8 + q + 4];
                a[mf][3] = A[(mr + 8) * 20 + t * 8 + q + 4];
            }
            const int k0r = t * 16 + 2 * q;
            #pragma unroll
            for (int nf = 0; nf < 4; nf++) {
                const int cb = nw + nf * 8 + r;
                uint32_t b0 = pack2(Bp[k0r * 132 + cb],       Bp[(k0r + 1) * 132 + cb]);
                uint32_t b1 = pack2(Bp[(k0r + 8) * 132 + cb], Bp[(k0r + 9) * 132 + cb]);
                mma_f16(acc[0][nf], a[0], b0, b1);
                mma_f16(acc[1][nf], a[1], b0, b1);
            }
        }
        __syncthreads();
        const int kn = (ks + 3) * 32;
        if (kn < SS) { K1_LOAD((ks + 3) & 3, kn); }
        CP_COMMIT();
    }

    #pragma unroll
    for (int nf = 0; nf < 4; nf++) {
        float2 bv = *(const float2*)(bias + n0 + nw + nf * 8 + 2 * q);
        #pragma unroll
        for (int mf = 0; mf < 2; mf++) {
            const int mr = m0 + mf * 16 + r;
            float* o0 = g_params + (size_t)mr * TOT + n0 + nw + nf * 8 + 2 * q;
            *(float2*)o0 = make_float2(acc[mf][nf][0] + bv.x, acc[mf][nf][1] + bv.y);
            float* o1 = g_params + (size_t)(mr + 8) * TOT + n0 + nw + nf * 8 + 2 * q;
            *(float2*)o1 = make_float2(acc[mf][nf][2] + bv.x, acc[mf][nf][3] + bv.y);
        }
    }
    #undef K1_LOAD
}

// ======================= kernel 2: normalize -> fp16 half2 swizzled layout =======================
__global__ __launch_bounds__(256) void k2_normalize() {
    __shared__ float sinv[256];
    __shared__ float part[4][64];
    const int b = blockIdx.x, tid = threadIdx.x;
    const float* P = g_params + (size_t)b * TOT;
    uint32_t* dst = g_wT + (size_t)b * WPB;

    #pragma unroll
    for (int m = 0; m < 2; m++) {
        const float* src = P + m * 16384;
        {
            float ss = 0.f;
            #pragma unroll 8
            for (int d = 0; d < 64; d++) { float v = src[d * 256 + tid]; ss += v * v; }
            sinv[tid] = 1.f / fmaxf(sqrtf(ss), 1e-12f);
        }
        __syncthreads();
        for (int idx = tid; idx < 8192; idx += 256) {
            int kp = idx >> 8, h = idx & 255;
            float inv = sinv[h];
            float a = src[(2 * kp) * 256 + h] * inv;
            float c = src[(2 * kp + 1) * 256 + h] * inv;
            dst[m * 8192 + kp * 256 + (h ^ ((kp & 3) << 3))] = pack2(a, c);
        }
        __syncthreads();
    }
    {
        const float* src = P + 32768;
        int q = tid >> 6, dd = tid & 63;
        float ss = 0.f;
        #pragma unroll 8
        for (int h = q * 64; h < q * 64 + 64; h++) { float v = src[h * 64 + dd]; ss += v * v; }
        part[q][dd] = ss;
        __syncthreads();
        if (tid < 64)
            sinv[tid] = 1.f / fmaxf(sqrtf(part[0][tid] + part[1][tid] + part[2][tid] + part[3][tid]), 1e-12f);
        __syncthreads();
        for (int idx = tid; idx < 8192; idx += 256) {
            int hp = idx >> 6, d = idx & 63;
            float inv = sinv[d];
            float a = src[(2 * hp) * 64 + d] * inv;
            float c = src[(2 * hp + 1) * 64 + d] * inv;
            dst[16384 + hp * 64 + (d ^ ((hp & 3) << 3))] = pack2(a, c);
        }
    }
}

// ======================= kernel 3: fp16 mma fused MLP, 1024 CTAs x 4 groups =======================
#define K3_SMEM ((24576 + 2304) * 4 + 8448 * 4)   // 141312 B

__global__ __launch_bounds__(256, 1) void k3_main(const float* __restrict__ x,
                                                  const float* __restrict__ scale,
                                                  float* __restrict__ out) {
    extern __shared__ uint32_t su[];
    uint32_t* xnw = su + 24576;              // [64][36] half2 words
    float* hs = (float*)(su + 26880);        // [64][132] fp32
    const int tid = threadIdx.x, w = tid >> 5, lane = tid & 31;
    const int b = blockIdx.x >> 4;           // 16 CTAs per batch
    const int gbase = (blockIdx.x & 15) * 4; // 4 groups of 64 rows per CTA
    const int hw = w >> 2, mw = w & 3, m0 = mw * 16;
    const int r = lane >> 2, q = lane & 3, q8 = q << 3;
    const int hoff = hw * 68;
    const uint32_t sb = smem_u32(su);

    // prefetch weights via cp.async (overlaps with group-0 RMS staging)
    {
        const uint32_t* wsrc = g_wT + (size_t)b * WPB;
        #pragma unroll 6
        for (int i = tid; i < 6144; i += 256)
            cpa16(sb + (uint32_t)i * 16, wsrc + i * 4);
        CP_COMMIT();
    }
    const int srow = tid >> 2, sqc = (tid & 3) * 16;
    float4 sc4[4];
    #pragma unroll
    for (int i = 0; i < 4; i++) sc4[i] = *(const float4*)(scale + sqc + 4 * i);

    const uint32_t* Wg = su;
    const uint32_t* Wv = su + 8192;
    const uint32_t* Wf = su + 16384;

    for (int g = 0; g < 4; g++) {
        const int row0 = (gbase + g) * 64;

        // ---- stage RMSNorm'd xn (fp16 RNE, half2-packed); keep residual in regs ----
        float4 xres[4];
        {
            const float4* xr = (const float4*)(x + ((size_t)b * NN + row0 + srow) * DD + sqc);
            float ssq = 0.f;
            #pragma unroll
            for (int i = 0; i < 4; i++) {
                xres[i] = xr[i];
                ssq += xres[i].x * xres[i].x + xres[i].y * xres[i].y
                     + xres[i].z * xres[i].z + xres[i].w * xres[i].w;
            }
            ssq += __shfl_xor_sync(0xffffffffu, ssq, 1);
            ssq += __shfl_xor_sync(0xffffffffu, ssq, 2);
            const float rr = rsqrtf(ssq * (1.0f / 64.0f) + 1e-6f);
            uint32_t* xd = xnw + srow * 36 + (tid & 3) * 8;
            #pragma unroll
            for (int i = 0; i < 4; i++) {
                xd[2 * i]     = pack2(xres[i].x * rr * sc4[i].x, xres[i].y * rr * sc4[i].y);
                xd[2 * i + 1] = pack2(xres[i].z * rr * sc4[i].z, xres[i].w * rr * sc4[i].w);
            }
        }
        if (g == 0) { CP_WAIT0(); }   // weights resident from here on
        __syncthreads();

        float oacc[8][4];
        #pragma unroll
        for (int i = 0; i < 8; i++) { oacc[i][0] = oacc[i][1] = oacc[i][2] = oacc[i][3] = 0.f; }

        #pragma unroll
        for (int ch = 0; ch < 2; ch++) {
            const int nb = hw * 128 + ch * 64;

            // ---- MMA1: gate/value [16 x 64] over k=64 (4 x k16) ----
            float ga[8][4], va[8][4];
            #pragma unroll
            for (int i = 0; i < 8; i++) {
                ga[i][0] = ga[i][1] = ga[i][2] = ga[i][3] = 0.f;
                va[i][0] = va[i][1] = va[i][2] = va[i][3] = 0.f;
            }
            #pragma unroll
            for (int kt = 0; kt < 4; kt++) {
                uint32_t xa[4];
                const uint32_t* xb = xnw + (m0 + r) * 36 + kt * 8 + q;
                xa[0] = xb[0];
                xa[1] = xb[8 * 36];
                xa[2] = xb[4];
                xa[3] = xb[8 * 36 + 4];
                const uint32_t* g0 = Wg + (kt * 8 + q) * 256;
                const uint32_t* g1 = Wg + (kt * 8 + q + 4) * 256;
                const uint32_t* v0 = Wv + (kt * 8 + q) * 256;
                const uint32_t* v1 = Wv + (kt * 8 + q + 4) * 256;
                #pragma unroll
                for (int nt = 0; nt < 8; nt++) {
                    const int c = ((nb + nt * 8) ^ q8) + r;
                    mma_f16(ga[nt], xa, g0[c], g1[c]);
                    mma_f16(va[nt], xa, v0[c], v1[c]);
                }
            }

            // ---- silu*value in regs; acc layout == A layout (f16 k16) -> MMA2 directly ----
            #pragma unroll
            for (int kt2 = 0; kt2 < 4; kt2++) {
                const int t0 = 2 * kt2, t1 = 2 * kt2 + 1;
                float h00 = 0.5f * ga[t0][0] * (1.f + tanha(0.5f * ga[t0][0])) * va[t0][0];
                float h01 = 0.5f * ga[t0][1] * (1.f + tanha(0.5f * ga[t0][1])) * va[t0][1];
                float h02 = 0.5f * ga[t0][2] * (1.f + tanha(0.5f * ga[t0][2])) * va[t0][2];
                float h03 = 0.5f * ga[t0][3] * (1.f + tanha(0.5f * ga[t0][3])) * va[t0][3];
                float h10 = 0.5f * ga[t1][0] * (1.f + tanha(0.5f * ga[t1][0])) * va[t1][0];
                float h11 = 0.5f * ga[t1][1] * (1.f + tanha(0.5f * ga[t1][1])) * va[t1][1];
                float h12 = 0.5f * ga[t1][2] * (1.f + tanha(0.5f * ga[t1][2])) * va[t1][2];
                float h13 = 0.5f * ga[t1][3] * (1.f + tanha(0.5f * ga[t1][3])) * va[t1][3];
                uint32_t ha[4];
                ha[0] = pack2(h00, h01);
                ha[1] = pack2(h02, h03);
                ha[2] = pack2(h10, h11);
                ha[3] = pack2(h12, h13);
                const int hp0 = (nb >> 1) + kt2 * 8;
                const uint32_t* f0 = Wf + (hp0 + q) * 64;
                const uint32_t* f1 = Wf + (hp0 + q + 4) * 64;
                #pragma unroll
                for (int dt = 0; dt < 8; dt++) {
                    const int c = ((dt * 8) ^ q8) + r;
                    mma_f16(oacc[dt], ha, f0[c], f1[c]);
                }
            }
        }

        // ---- stash out partials ----
        #pragma unroll
        for (int dt = 0; dt < 8; dt++) {
            *(float2*)&hs[(m0 + r) * 132 + hoff + dt * 8 + 2 * q]     = make_float2(oacc[dt][0], oacc[dt][1]);
            *(float2*)&hs[(m0 + r + 8) * 132 + hoff + dt * 8 + 2 * q] = make_float2(oacc[dt][2], oacc[dt][3]);
        }
        __syncthreads();

        // ---- reduce halves + residual (regs) + store ----
        {
            float* orow = out + ((size_t)b * NN + row0 + srow) * DD + sqc;
            #pragma unroll
            for (int i = 0; i < 4; i++) {
                float4 a = *(const float4*)&hs[srow * 132 + sqc + 4 * i];
                float4 c = *(const float4*)&hs[srow * 132 + 68 + sqc + 4 * i];
                *(float4*)(orow + 4 * i) = make_float4(a.x + c.x + xres[i].x, a.y + c.y + xres[i].y,
                                                       a.z + c.z + xres[i].z, a.w + c.w + xres[i].w);
            }
        }
        __syncthreads();
    }
}

// ======================= launch =======================
extern "C" void kernel_launch(void* const* d_in, const int* in_sizes, int n_in,
                              void* d_out, int out_size) {
    const float* x     = (const float*)d_in[0];
    const float* s     = (const float*)d_in[1];
    const float* W     = (const float*)d_in[2];
    const float* bias  = (const float*)d_in[3];
    const float* scale = (const float*)d_in[4];
    float* out = (float*)d_out;

    k0_pack_s<<<dim3(16), 256>>>(s);

    cudaFuncSetAttribute(k1_mma, cudaFuncAttributeMaxDynamicSharedMemorySize, K1_SMEM);
    k1_mma<<<dim3(TOT / 128), 256, K1_SMEM>>>(W, bias);

    k2_normalize<<<dim3(BB), 256>>>();

    cudaFuncSetAttribute(k3_main, cudaFuncAttributeMaxDynamicSharedMemorySize, K3_SMEM);
    k3_main<<<dim3(1024), 256, K3_SMEM>>>(x, scale, out);
}